// round 1
// baseline (speedup 1.0000x reference)
#include <cuda_runtime.h>
#include <math.h>
#include <stdint.h>

#define BB   2
#define NN   768
#define TT   96
#define FMF  8
#define HIDD 64
#define TDD  32

#define NTILE 24           // 768/32
#define NUPPER 300         // 24*25/2

// Scratch (allocation-free rule: __device__ globals)
__device__ float g_h[BB * NN * HIDD];
__device__ float g_P[BB * NN * HIDD];   // s_i + ps_b1
__device__ float g_Q[BB * NN * HIDD];   // s_j

// ---------------------------------------------------------------------------
// Kernel 1: per-node feature pipeline. One block (64 threads) per node.
// ---------------------------------------------------------------------------
__global__ __launch_bounds__(64)
void node_kernel(const float* __restrict__ x_hist, const float* __restrict__ x_mark,
                 const float* __restrict__ te_w1, const float* __restrict__ te_b1,
                 const float* __restrict__ te_w2, const float* __restrict__ te_b2,
                 const float* __restrict__ me_w1, const float* __restrict__ me_b1,
                 const float* __restrict__ me_w2, const float* __restrict__ me_b2,
                 const float* __restrict__ nf_w,  const float* __restrict__ nf_b,
                 const float* __restrict__ ps_w1, const float* __restrict__ ps_b1)
{
    const int node = blockIdx.x;          // 0..B*N-1
    const int tid  = threadIdx.x;         // 0..63

    __shared__ float redS[64], redM[64];
    __shared__ float st[3], msum[8];
    __shared__ float t1[TDD], m1[TDD];
    __shared__ float hcat[HIDD], hsm[HIDD];

    const float* xh = x_hist + (size_t)node * TT;
    const float* xm = x_mark + (size_t)node * TT * FMF;

    // stats over T: sum & max
    float s = 0.f, mx = -3.0e38f;
    for (int t = tid; t < TT; t += 64) { float v = xh[t]; s += v; mx = fmaxf(mx, v); }

    // mark partial sums: feature f = tid&7, t-group = tid>>3 (8 groups)
    float ms = 0.f;
    {
        int f = tid & 7, t0 = tid >> 3;
        for (int t = t0; t < TT; t += 8) ms += xm[t * FMF + f];
    }

    redS[tid] = s; redM[tid] = mx;
    __syncthreads();
    for (int off = 32; off > 0; off >>= 1) {
        if (tid < off) {
            redS[tid] += redS[tid + off];
            redM[tid] = fmaxf(redM[tid], redM[tid + off]);
        }
        __syncthreads();
    }
    if (tid == 0) {
        st[0] = xh[TT - 1];
        st[1] = redS[0] / (float)TT;
        st[2] = redM[0];
    }
    __syncthreads();

    redS[tid] = ms;
    __syncthreads();
    if (tid < 8) {
        float a = 0.f;
        #pragma unroll
        for (int g = 0; g < 8; g++) a += redS[tid + 8 * g];
        msum[tid] = a / (float)TT;
    }
    __syncthreads();

    // layer 1: time branch (threads 0-31) and mark branch (threads 32-63)
    if (tid < TDD) {
        float a = te_b1[tid];
        #pragma unroll
        for (int c = 0; c < 3; c++) a = fmaf(st[c], te_w1[c * TDD + tid], a);
        t1[tid] = fmaxf(a, 0.f);
    } else {
        int k = tid - TDD;
        float a = me_b1[k];
        #pragma unroll
        for (int c = 0; c < FMF; c++) a = fmaf(msum[c], me_w1[c * TDD + k], a);
        m1[k] = fmaxf(a, 0.f);
    }
    __syncthreads();

    // layer 2
    if (tid < TDD) {
        float a = te_b2[tid];
        #pragma unroll
        for (int c = 0; c < TDD; c++) a = fmaf(t1[c], te_w2[c * TDD + tid], a);
        hcat[tid] = a;
    } else {
        int k = tid - TDD;
        float a = me_b2[k];
        #pragma unroll
        for (int c = 0; c < TDD; c++) a = fmaf(m1[c], me_w2[c * TDD + k], a);
        hcat[TDD + k] = a;
    }
    __syncthreads();

    // node fuse: h = relu(hcat @ nf_w + nf_b)
    {
        float a = nf_b[tid];
        #pragma unroll
        for (int c = 0; c < HIDD; c++) a = fmaf(hcat[c], nf_w[c * HIDD + tid], a);
        float hk = fmaxf(a, 0.f);
        hsm[tid] = hk;
        g_h[(size_t)node * HIDD + tid] = hk;
    }
    __syncthreads();

    // P = h @ w_i + ps_b1 ;  Q = h @ w_j
    {
        float p = ps_b1[tid], q = 0.f;
        #pragma unroll
        for (int c = 0; c < HIDD; c++) {
            float hc = hsm[c];
            p = fmaf(hc, ps_w1[c * HIDD + tid], p);
            q = fmaf(hc, ps_w1[(HIDD + c) * HIDD + tid], q);
        }
        g_P[(size_t)node * HIDD + tid] = p;
        g_Q[(size_t)node * HIDD + tid] = q;
    }
}

// ---------------------------------------------------------------------------
// Kernel 2: pairwise delta. Upper-triangular 32x32 tiles; each computed pair
// writes both (i,j) and (j,i). Diagonal entries written as 0.
// ---------------------------------------------------------------------------
#define PAD 65
#define SM_FLOATS (6 * 32 * PAD + 64 * 64 + 64)

__global__ __launch_bounds__(256, 2)
void pair_kernel(const float* __restrict__ ps_w1, const float* __restrict__ ps_w2,
                 const float* __restrict__ ps_b2, float* __restrict__ out)
{
    extern __shared__ float sm[];
    float* hI  = sm;                    // [32][65]
    float* hJ  = hI  + 32 * PAD;
    float* PI  = hJ  + 32 * PAD;
    float* QI  = PI  + 32 * PAD;
    float* PJ  = QI  + 32 * PAD;
    float* QJ  = PJ  + 32 * PAD;
    float* wdT = QJ  + 32 * PAD;        // [64][64]: wdT[k][c] = w_d[c][k]
    float* w2s = wdT + 64 * 64;         // [64]

    const int tid = threadIdx.x;
    const int b   = blockIdx.y;

    // decode upper-triangular tile index
    int u = blockIdx.x, ti = 0;
    while (u >= NTILE - ti) { u -= NTILE - ti; ti++; }
    const int tj = ti + u;

    const int baseI = (b * NN + ti * 32) * HIDD;
    const int baseJ = (b * NN + tj * 32) * HIDD;

    for (int e = tid; e < 32 * HIDD; e += 256) {
        int r = e >> 6, c = e & 63;
        hI[r * PAD + c] = g_h[baseI + e];
        hJ[r * PAD + c] = g_h[baseJ + e];
        PI[r * PAD + c] = g_P[baseI + e];
        QI[r * PAD + c] = g_Q[baseI + e];
        PJ[r * PAD + c] = g_P[baseJ + e];
        QJ[r * PAD + c] = g_Q[baseJ + e];
    }
    for (int e = tid; e < 64 * 64; e += 256) {
        int k = e >> 6, c = e & 63;
        wdT[k * 64 + c] = ps_w1[(128 + c) * HIDD + k];
    }
    if (tid < 64) w2s[tid] = ps_w2[tid];
    const float b2v = ps_b2[0];
    __syncthreads();

    float* ob = out + (size_t)b * NN * NN;

    #pragma unroll 1
    for (int r = 0; r < 4; r++) {
        const int p = tid + 256 * r;
        const int i = p >> 5;           // warp-uniform
        const int j = p & 31;           // = lane
        const int gi = ti * 32 + i, gj = tj * 32 + j;

        if (ti == tj) {
            if (i == j) { ob[(size_t)gi * NN + gj] = 0.f; continue; }
            if (i > j) continue;        // written by symmetric pair
        }

        float diff[64];
        #pragma unroll
        for (int c = 0; c < 64; c++)
            diff[c] = fabsf(hI[i * PAD + c] - hJ[j * PAD + c]);

        float tij = b2v, tji = b2v;
        const int iP = i * PAD, jP = j * PAD;

        #pragma unroll 2
        for (int k = 0; k < 64; k++) {
            const float4* wc = reinterpret_cast<const float4*>(wdT + (k << 6));
            float acc[8];
            #pragma unroll
            for (int a = 0; a < 8; a++) acc[a] = 0.f;
            #pragma unroll
            for (int c4 = 0; c4 < 16; c4++) {
                float4 w = wc[c4];
                int a = c4 & 7;
                acc[a] = fmaf(diff[4 * c4 + 0], w.x, acc[a]);
                acc[a] = fmaf(diff[4 * c4 + 1], w.y, acc[a]);
                acc[a] = fmaf(diff[4 * c4 + 2], w.z, acc[a]);
                acc[a] = fmaf(diff[4 * c4 + 3], w.w, acc[a]);
            }
            float dk = ((acc[0] + acc[1]) + (acc[2] + acc[3]))
                     + ((acc[4] + acc[5]) + (acc[6] + acc[7]));

            float aij = dk + PI[iP + k] + QJ[jP + k];
            float aji = dk + PJ[jP + k] + QI[iP + k];
            float wk  = w2s[k];
            tij = fmaf(fmaxf(aij, 0.f), wk, tij);
            tji = fmaf(fmaxf(aji, 0.f), wk, tji);
        }

        float d = 0.5f * (tanhf(tij) + tanhf(tji));
        ob[(size_t)gi * NN + gj] = d;
        ob[(size_t)gj * NN + gi] = d;
    }
}

// ---------------------------------------------------------------------------
// Kernel 3: a = relu(a_static + lam*delta); row-normalize; write lam.
// In-place on d_out (delta was staged there by pair_kernel).
// ---------------------------------------------------------------------------
__global__ __launch_bounds__(256)
void finalize_kernel(const float* __restrict__ a_static,
                     const float* __restrict__ raw_lambda,
                     float* __restrict__ out, int out_size)
{
    const int row = blockIdx.x;           // 0..B*N-1
    const int b = row / NN, i = row % NN;
    const int tid = threadIdx.x;

    const float lam = 1.f / (1.f + expf(-raw_lambda[0]));
    float* orow = out + ((size_t)b * NN + i) * NN;
    const float* arow = a_static + (size_t)i * NN;

    float v[3];
    float s = 0.f;
    #pragma unroll
    for (int r = 0; r < 3; r++) {
        int j = tid + 256 * r;
        float a = fmaxf(fmaf(lam, orow[j], arow[j]), 0.f);
        v[r] = a;
        s += a;
    }

    __shared__ float red[256];
    red[tid] = s;
    __syncthreads();
    for (int off = 128; off > 0; off >>= 1) {
        if (tid < off) red[tid] += red[tid + off];
        __syncthreads();
    }
    float inv = 1.f / fmaxf(red[0], 1e-6f);
    #pragma unroll
    for (int r = 0; r < 3; r++) orow[tid + 256 * r] = v[r] * inv;

    if (row == 0 && tid == 0) {
        for (int idx = BB * NN * NN; idx < out_size; idx++) out[idx] = lam;
    }
}

// ---------------------------------------------------------------------------
extern "C" void kernel_launch(void* const* d_in, const int* in_sizes, int n_in,
                              void* d_out, int out_size)
{
    const float* x_hist   = (const float*)d_in[0];
    const float* x_mark   = (const float*)d_in[1];
    const float* a_static = (const float*)d_in[2];
    const float* te_w1 = (const float*)d_in[3];
    const float* te_b1 = (const float*)d_in[4];
    const float* te_w2 = (const float*)d_in[5];
    const float* te_b2 = (const float*)d_in[6];
    const float* me_w1 = (const float*)d_in[7];
    const float* me_b1 = (const float*)d_in[8];
    const float* me_w2 = (const float*)d_in[9];
    const float* me_b2 = (const float*)d_in[10];
    const float* nf_w  = (const float*)d_in[11];
    const float* nf_b  = (const float*)d_in[12];
    const float* ps_w1 = (const float*)d_in[13];
    const float* ps_b1 = (const float*)d_in[14];
    const float* ps_w2 = (const float*)d_in[15];
    const float* ps_b2 = (const float*)d_in[16];
    const float* raw_lambda = (const float*)d_in[17];
    float* out = (float*)d_out;

    static bool attr_set = false;
    if (!attr_set) {
        cudaFuncSetAttribute(pair_kernel,
                             cudaFuncAttributeMaxDynamicSharedMemorySize,
                             SM_FLOATS * (int)sizeof(float));
        attr_set = true;
    }

    node_kernel<<<BB * NN, 64>>>(x_hist, x_mark, te_w1, te_b1, te_w2, te_b2,
                                 me_w1, me_b1, me_w2, me_b2, nf_w, nf_b,
                                 ps_w1, ps_b1);

    dim3 grid2(NUPPER, BB);
    pair_kernel<<<grid2, 256, SM_FLOATS * (int)sizeof(float)>>>(ps_w1, ps_w2, ps_b2, out);

    finalize_kernel<<<BB * NN, 256>>>(a_static, raw_lambda, out, out_size);
}

// round 4
// speedup vs baseline: 3.0924x; 3.0924x over previous
#include <cuda_runtime.h>
#include <math.h>
#include <stdint.h>

#define BB   2
#define NN   768
#define TT   96
#define FMF  8
#define HIDD 64
#define TDD  32

#define NTILE 24           // 768/32
#define NUPPER 300         // 24*25/2
#define PAD 68             // word-pad so (4*row + col) & 31 is lane-unique

// ---------------------------------------------------------------------------
// helpers
// ---------------------------------------------------------------------------
__device__ __forceinline__ uint32_t f2tf32(float f) {
    uint32_t r; asm("cvt.rna.tf32.f32 %0, %1;" : "=r"(r) : "f"(f)); return r;
}

__device__ __forceinline__ void mma_tf32(float* d,
                                         uint32_t a0, uint32_t a1, uint32_t a2, uint32_t a3,
                                         uint32_t b0, uint32_t b1) {
    asm volatile(
        "mma.sync.aligned.m16n8k8.row.col.f32.tf32.tf32.f32 "
        "{%0,%1,%2,%3}, {%4,%5,%6,%7}, {%8,%9}, {%0,%1,%2,%3};"
        : "+f"(d[0]), "+f"(d[1]), "+f"(d[2]), "+f"(d[3])
        : "r"(a0), "r"(a1), "r"(a2), "r"(a3), "r"(b0), "r"(b1));
}

// Scratch (allocation-free rule: __device__ globals)
__device__ float g_h[BB * NN * HIDD];
__device__ float g_P[BB * NN * HIDD];   // h @ w_i + ps_b1
__device__ float g_Q[BB * NN * HIDD];   // h @ w_j

// ---------------------------------------------------------------------------
// Kernel 1: per-node features. 4 nodes per 256-thread block.
// ---------------------------------------------------------------------------
__global__ __launch_bounds__(256)
void node_kernel(const float* __restrict__ x_hist, const float* __restrict__ x_mark,
                 const float* __restrict__ te_w1, const float* __restrict__ te_b1,
                 const float* __restrict__ te_w2, const float* __restrict__ te_b2,
                 const float* __restrict__ me_w1, const float* __restrict__ me_b1,
                 const float* __restrict__ me_w2, const float* __restrict__ me_b2,
                 const float* __restrict__ nf_w,  const float* __restrict__ nf_b,
                 const float* __restrict__ ps_w1, const float* __restrict__ ps_b1)
{
    const int tid = threadIdx.x;
    const int grp = tid >> 6;             // 0..3
    const int g   = tid & 63;
    const int node = blockIdx.x * 4 + grp;

    __shared__ float redS[4][64], redM[4][64];
    __shared__ float st[4][3], msum[4][8];
    __shared__ float t1[4][TDD], m1[4][TDD];
    __shared__ float hcat[4][HIDD], hsm[4][HIDD];

    const float* xh = x_hist + (size_t)node * TT;
    const float* xm = x_mark + (size_t)node * TT * FMF;

    float s = 0.f, mx = -3.0e38f;
    for (int t = g; t < TT; t += 64) { float v = xh[t]; s += v; mx = fmaxf(mx, v); }

    float ms = 0.f;
    {
        int f = g & 7, t0 = g >> 3;
        for (int t = t0; t < TT; t += 8) ms += xm[t * FMF + f];
    }

    redS[grp][g] = s; redM[grp][g] = mx;
    __syncthreads();
    for (int off = 32; off > 0; off >>= 1) {
        if (g < off) {
            redS[grp][g] += redS[grp][g + off];
            redM[grp][g] = fmaxf(redM[grp][g], redM[grp][g + off]);
        }
        __syncthreads();
    }
    if (g == 0) {
        st[grp][0] = xh[TT - 1];
        st[grp][1] = redS[grp][0] / (float)TT;
        st[grp][2] = redM[grp][0];
    }
    __syncthreads();

    redS[grp][g] = ms;
    __syncthreads();
    if (g < 8) {
        float a = 0.f;
        #pragma unroll
        for (int q = 0; q < 8; q++) a += redS[grp][g + 8 * q];
        msum[grp][g] = a / (float)TT;
    }
    __syncthreads();

    if (g < TDD) {
        float a = te_b1[g];
        #pragma unroll
        for (int c = 0; c < 3; c++) a = fmaf(st[grp][c], te_w1[c * TDD + g], a);
        t1[grp][g] = fmaxf(a, 0.f);
    } else {
        int k = g - TDD;
        float a = me_b1[k];
        #pragma unroll
        for (int c = 0; c < FMF; c++) a = fmaf(msum[grp][c], me_w1[c * TDD + k], a);
        m1[grp][k] = fmaxf(a, 0.f);
    }
    __syncthreads();

    if (g < TDD) {
        float a = te_b2[g];
        #pragma unroll
        for (int c = 0; c < TDD; c++) a = fmaf(t1[grp][c], te_w2[c * TDD + g], a);
        hcat[grp][g] = a;
    } else {
        int k = g - TDD;
        float a = me_b2[k];
        #pragma unroll
        for (int c = 0; c < TDD; c++) a = fmaf(m1[grp][c], me_w2[c * TDD + k], a);
        hcat[grp][TDD + k] = a;
    }
    __syncthreads();

    {
        float a = nf_b[g];
        #pragma unroll
        for (int c = 0; c < HIDD; c++) a = fmaf(hcat[grp][c], nf_w[c * HIDD + g], a);
        float hk = fmaxf(a, 0.f);
        hsm[grp][g] = hk;
        g_h[(size_t)node * HIDD + g] = hk;
    }
    __syncthreads();

    {
        float p = ps_b1[g], q = 0.f;
        #pragma unroll
        for (int c = 0; c < HIDD; c++) {
            float hc = hsm[grp][c];
            p = fmaf(hc, ps_w1[c * HIDD + g], p);
            q = fmaf(hc, ps_w1[(HIDD + c) * HIDD + g], q);
        }
        g_P[(size_t)node * HIDD + g] = p;
        g_Q[(size_t)node * HIDD + g] = q;
    }
}

// ---------------------------------------------------------------------------
// Kernel 2: pairwise delta via legacy tf32 mma.sync (HMMA).
// Block = 256 threads = 8 warps. Warp w, iteration it: fixed i = it*8 + w,
// computes dk[j][k] (32x64) = |h_i - h_j| @ w_d via m16n8k8 tf32 MMA,
// then relu-dot-tanh epilogue for both (i,j) and (j,i).
// ---------------------------------------------------------------------------
#define BF_BYTES (64 * 32 * 8)                       // fragment table, 16 KB
#define SM_BYTES (BF_BYTES + (6 * 32 * PAD + 64) * 4)

__global__ __launch_bounds__(256, 2)
void pair_kernel(const float* __restrict__ ps_w1, const float* __restrict__ ps_w2,
                 const float* __restrict__ ps_b2, float* __restrict__ out)
{
    extern __shared__ __align__(16) char smx[];
    uint2* Bf = (uint2*)smx;                         // [kt*8+nt][lane] = (b0,b1) tf32
    float* fp = (float*)(smx + BF_BYTES);
    float* hI  = fp;                                 // [32][PAD]
    float* hJ  = hI + 32 * PAD;
    float* PI  = hJ + 32 * PAD;
    float* QI  = PI + 32 * PAD;
    float* PJ  = QI + 32 * PAD;
    float* QJ  = PJ + 32 * PAD;
    float* w2s = QJ + 32 * PAD;                      // [64]

    const int tid  = threadIdx.x;
    const int b    = blockIdx.y;
    const int w    = tid >> 5;
    const int lane = tid & 31;
    const int gid  = lane >> 2;                      // 0..7
    const int tig  = lane & 3;                       // 0..3

    // decode upper-triangular tile index
    int u = blockIdx.x, ti = 0;
    while (u >= NTILE - ti) { u -= NTILE - ti; ti++; }
    const int tj = ti + u;

    const int baseI = (b * NN + ti * 32) * HIDD;
    const int baseJ = (b * NN + tj * 32) * HIDD;

    for (int e = tid; e < 32 * HIDD; e += 256) {
        int r = e >> 6, c = e & 63;
        hI[r * PAD + c] = g_h[baseI + e];
        hJ[r * PAD + c] = g_h[baseJ + e];
        PI[r * PAD + c] = g_P[baseI + e];
        QI[r * PAD + c] = g_Q[baseI + e];
        PJ[r * PAD + c] = g_P[baseJ + e];
        QJ[r * PAD + c] = g_Q[baseJ + e];
    }
    // B fragment table: b0 = w_d[kt*8+tg][nt*8+gd], b1 = w_d[kt*8+tg+4][nt*8+gd]
    for (int e = tid; e < 64 * 32; e += 256) {
        int ktnt = e >> 5, ln = e & 31;
        int kt = ktnt >> 3, nt = ktnt & 7;
        int gd = ln >> 2, tg = ln & 3;
        int c0 = kt * 8 + tg, n = nt * 8 + gd;
        uint2 v;
        v.x = f2tf32(ps_w1[(128 + c0) * HIDD + n]);
        v.y = f2tf32(ps_w1[(128 + c0 + 4) * HIDD + n]);
        Bf[(size_t)ktnt * 32 + ln] = v;
    }
    if (tid < 64) w2s[tid] = ps_w2[tid];
    const float b2v = ps_b2[0];
    __syncthreads();

    float* ob = out + (size_t)b * NN * NN;

    #pragma unroll 1
    for (int it = 0; it < 4; it++) {
        const int i  = it * 8 + w;                   // warp-uniform tile row
        const int iP = i * PAD;

        float sij[4], sji[4];                        // per j-row partials
        #pragma unroll
        for (int rr = 0; rr < 4; rr++) { sij[rr] = 0.f; sji[rr] = 0.f; }

        #pragma unroll 1
        for (int nh = 0; nh < 2; nh++) {
            float acc[2][4][4];
            #pragma unroll
            for (int mt = 0; mt < 2; mt++)
                #pragma unroll
                for (int n = 0; n < 4; n++)
                    #pragma unroll
                    for (int x = 0; x < 4; x++) acc[mt][n][x] = 0.f;

            #pragma unroll
            for (int kt = 0; kt < 8; kt++) {
                const int c0 = kt * 8 + tig, c1 = c0 + 4;
                const float hi0 = hI[iP + c0], hi1 = hI[iP + c1];
                const int r0 = gid * PAD, r1 = (gid + 8) * PAD,
                          r2 = (gid + 16) * PAD, r3 = (gid + 24) * PAD;
                uint32_t A00 = f2tf32(fabsf(hi0 - hJ[r0 + c0]));
                uint32_t A01 = f2tf32(fabsf(hi0 - hJ[r1 + c0]));
                uint32_t A02 = f2tf32(fabsf(hi1 - hJ[r0 + c1]));
                uint32_t A03 = f2tf32(fabsf(hi1 - hJ[r1 + c1]));
                uint32_t A10 = f2tf32(fabsf(hi0 - hJ[r2 + c0]));
                uint32_t A11 = f2tf32(fabsf(hi0 - hJ[r3 + c0]));
                uint32_t A12 = f2tf32(fabsf(hi1 - hJ[r2 + c1]));
                uint32_t A13 = f2tf32(fabsf(hi1 - hJ[r3 + c1]));
                #pragma unroll
                for (int ntl = 0; ntl < 4; ntl++) {
                    uint2 bv = Bf[(size_t)(kt * 8 + nh * 4 + ntl) * 32 + lane];
                    mma_tf32(acc[0][ntl], A00, A01, A02, A03, bv.x, bv.y);
                    mma_tf32(acc[1][ntl], A10, A11, A12, A13, bv.x, bv.y);
                }
            }

            // epilogue for this N-half: cols k0 = nt*8 + tig*2 (+1)
            #pragma unroll
            for (int ntl = 0; ntl < 4; ntl++) {
                const int k0 = (nh * 4 + ntl) * 8 + tig * 2;
                const float2 piv = *(const float2*)&PI[iP + k0];
                const float2 qiv = *(const float2*)&QI[iP + k0];
                const float2 w2v = *(const float2*)&w2s[k0];
                #pragma unroll
                for (int rr = 0; rr < 4; rr++) {
                    const int row = gid + 8 * rr;
                    const float dk0 = acc[rr >> 1][ntl][(rr & 1) * 2];
                    const float dk1 = acc[rr >> 1][ntl][(rr & 1) * 2 + 1];
                    const float2 qjv = *(const float2*)&QJ[row * PAD + k0];
                    const float2 pjv = *(const float2*)&PJ[row * PAD + k0];
                    sij[rr] = fmaf(fmaxf(dk0 + piv.x + qjv.x, 0.f), w2v.x, sij[rr]);
                    sij[rr] = fmaf(fmaxf(dk1 + piv.y + qjv.y, 0.f), w2v.y, sij[rr]);
                    sji[rr] = fmaf(fmaxf(dk0 + pjv.x + qiv.x, 0.f), w2v.x, sji[rr]);
                    sji[rr] = fmaf(fmaxf(dk1 + pjv.y + qiv.y, 0.f), w2v.y, sji[rr]);
                }
            }
        }

        // reduce across the 4-lane group (tig 0..3); bias added ONCE after
        #pragma unroll
        for (int rr = 0; rr < 4; rr++) {
            sij[rr] += __shfl_xor_sync(0xFFFFFFFF, sij[rr], 1);
            sij[rr] += __shfl_xor_sync(0xFFFFFFFF, sij[rr], 2);
            sji[rr] += __shfl_xor_sync(0xFFFFFFFF, sji[rr], 1);
            sji[rr] += __shfl_xor_sync(0xFFFFFFFF, sji[rr], 2);
        }

        // lane tig handles row j = gid + 8*tig
        const int j  = gid + 8 * tig;
        const int gi = ti * 32 + i, gj = tj * 32 + j;
        const float a_ij = sij[tig] + b2v;
        const float a_ji = sji[tig] + b2v;
        if (ti != tj || i < j) {
            float d = 0.5f * (tanhf(a_ij) + tanhf(a_ji));
            ob[(size_t)gi * NN + gj] = d;
            ob[(size_t)gj * NN + gi] = d;
        } else if (i == j) {
            ob[(size_t)gi * NN + gj] = 0.f;
        }
    }
}

// ---------------------------------------------------------------------------
// Kernel 3: a = relu(a_static + lam*delta); row-normalize; write lam.
// ---------------------------------------------------------------------------
__global__ __launch_bounds__(256)
void finalize_kernel(const float* __restrict__ a_static,
                     const float* __restrict__ raw_lambda,
                     float* __restrict__ out, int out_size)
{
    const int row = blockIdx.x;
    const int b = row / NN, i = row % NN;
    const int tid = threadIdx.x;

    const float lam = 1.f / (1.f + expf(-raw_lambda[0]));
    float* orow = out + ((size_t)b * NN + i) * NN;
    const float* arow = a_static + (size_t)i * NN;

    float v[3];
    float s = 0.f;
    #pragma unroll
    for (int r = 0; r < 3; r++) {
        int j = tid + 256 * r;
        float a = fmaxf(fmaf(lam, orow[j], arow[j]), 0.f);
        v[r] = a;
        s += a;
    }

    __shared__ float red[256];
    red[tid] = s;
    __syncthreads();
    for (int off = 128; off > 0; off >>= 1) {
        if (tid < off) red[tid] += red[tid + off];
        __syncthreads();
    }
    float inv = 1.f / fmaxf(red[0], 1e-6f);
    #pragma unroll
    for (int r = 0; r < 3; r++) orow[tid + 256 * r] = v[r] * inv;

    if (row == 0 && tid == 0) {
        for (int idx = BB * NN * NN; idx < out_size; idx++) out[idx] = lam;
    }
}

// ---------------------------------------------------------------------------
extern "C" void kernel_launch(void* const* d_in, const int* in_sizes, int n_in,
                              void* d_out, int out_size)
{
    const float* x_hist   = (const float*)d_in[0];
    const float* x_mark   = (const float*)d_in[1];
    const float* a_static = (const float*)d_in[2];
    const float* te_w1 = (const float*)d_in[3];
    const float* te_b1 = (const float*)d_in[4];
    const float* te_w2 = (const float*)d_in[5];
    const float* te_b2 = (const float*)d_in[6];
    const float* me_w1 = (const float*)d_in[7];
    const float* me_b1 = (const float*)d_in[8];
    const float* me_w2 = (const float*)d_in[9];
    const float* me_b2 = (const float*)d_in[10];
    const float* nf_w  = (const float*)d_in[11];
    const float* nf_b  = (const float*)d_in[12];
    const float* ps_w1 = (const float*)d_in[13];
    const float* ps_b1 = (const float*)d_in[14];
    const float* ps_w2 = (const float*)d_in[15];
    const float* ps_b2 = (const float*)d_in[16];
    const float* raw_lambda = (const float*)d_in[17];
    float* out = (float*)d_out;

    static bool attr_set = false;
    if (!attr_set) {
        cudaFuncSetAttribute(pair_kernel,
                             cudaFuncAttributeMaxDynamicSharedMemorySize, SM_BYTES);
        attr_set = true;
    }

    node_kernel<<<BB * NN / 4, 256>>>(x_hist, x_mark, te_w1, te_b1, te_w2, te_b2,
                                      me_w1, me_b1, me_w2, me_b2, nf_w, nf_b,
                                      ps_w1, ps_b1);

    dim3 grid2(NUPPER, BB);
    pair_kernel<<<grid2, 256, SM_BYTES>>>(ps_w1, ps_w2, ps_b2, out);

    finalize_kernel<<<BB * NN, 256>>>(a_static, raw_lambda, out, out_size);
}

// round 5
// speedup vs baseline: 3.2402x; 1.0478x over previous
#include <cuda_runtime.h>
#include <math.h>
#include <stdint.h>

#define BB   2
#define NN   768
#define TT   96
#define FMF  8
#define HIDD 64
#define TDD  32

#define NTILE 24           // 768/32
#define NUPPER 300         // 24*25/2
#define PAD 68             // word-pad so (4*row + col) & 31 is lane-unique

// ---------------------------------------------------------------------------
// helpers
// ---------------------------------------------------------------------------
__device__ __forceinline__ uint32_t f2tf32(float f) {
    uint32_t r; asm("cvt.rna.tf32.f32 %0, %1;" : "=r"(r) : "f"(f)); return r;
}

__device__ __forceinline__ void mma_tf32(float* d,
                                         uint32_t a0, uint32_t a1, uint32_t a2, uint32_t a3,
                                         uint32_t b0, uint32_t b1) {
    asm volatile(
        "mma.sync.aligned.m16n8k8.row.col.f32.tf32.tf32.f32 "
        "{%0,%1,%2,%3}, {%4,%5,%6,%7}, {%8,%9}, {%0,%1,%2,%3};"
        : "+f"(d[0]), "+f"(d[1]), "+f"(d[2]), "+f"(d[3])
        : "r"(a0), "r"(a1), "r"(a2), "r"(a3), "r"(b0), "r"(b1));
}

// Scratch (allocation-free rule: __device__ globals)
__device__ float g_h[BB * NN * HIDD];
__device__ float g_P[BB * NN * HIDD];   // h @ w_i + ps_b1
__device__ float g_Q[BB * NN * HIDD];   // h @ w_j

// ---------------------------------------------------------------------------
// Kernel 1: per-node features. ONE WARP per node; shuffle-only, no barriers.
// Lane owns output channels 2*lane and 2*lane+1 of each 64-wide stage.
// ---------------------------------------------------------------------------
__global__ __launch_bounds__(256)
void node_kernel(const float* __restrict__ x_hist, const float* __restrict__ x_mark,
                 const float* __restrict__ te_w1, const float* __restrict__ te_b1,
                 const float* __restrict__ te_w2, const float* __restrict__ te_b2,
                 const float* __restrict__ me_w1, const float* __restrict__ me_b1,
                 const float* __restrict__ me_w2, const float* __restrict__ me_b2,
                 const float* __restrict__ nf_w,  const float* __restrict__ nf_b,
                 const float* __restrict__ ps_w1, const float* __restrict__ ps_b1)
{
    const int lane = threadIdx.x & 31;
    const int node = blockIdx.x * 8 + (threadIdx.x >> 5);

    const float* xh = x_hist + (size_t)node * TT;
    const float* xm = x_mark + (size_t)node * TT * FMF;

    // ---- stats over T = 96 = 3*32 ----
    float v0 = xh[lane], v1 = xh[lane + 32], v2 = xh[lane + 64];
    float s  = v0 + v1 + v2;
    float mx = fmaxf(v0, fmaxf(v1, v2));
    #pragma unroll
    for (int off = 16; off > 0; off >>= 1) {
        s  += __shfl_xor_sync(0xFFFFFFFF, s, off);
        mx  = fmaxf(mx, __shfl_xor_sync(0xFFFFFFFF, mx, off));
    }
    const float st0 = __shfl_sync(0xFFFFFFFF, v2, 31);   // xh[95]
    const float st1 = s * (1.f / (float)TT);
    const float st2 = mx;

    // ---- mark mean: 768 = 32*24 coalesced; lane l accumulates feature l&7 ----
    float ms = 0.f;
    #pragma unroll
    for (int q = 0; q < 24; q++) ms += xm[lane + 32 * q];
    ms += __shfl_xor_sync(0xFFFFFFFF, ms, 8);
    ms += __shfl_xor_sync(0xFFFFFFFF, ms, 16);
    ms *= (1.f / (float)TT);          // lane l holds msum[l & 7]

    // ---- layer 1 (both branches per lane) ----
    float t1 = te_b1[lane];
    t1 = fmaf(st0, te_w1[lane], t1);
    t1 = fmaf(st1, te_w1[32 + lane], t1);
    t1 = fmaf(st2, te_w1[64 + lane], t1);
    t1 = fmaxf(t1, 0.f);

    float m1 = me_b1[lane];
    #pragma unroll
    for (int c = 0; c < FMF; c++)
        m1 = fmaf(__shfl_sync(0xFFFFFFFF, ms, c), me_w1[c * TDD + lane], m1);
    m1 = fmaxf(m1, 0.f);

    // ---- layer 2 ----
    float t2 = te_b2[lane], m2 = me_b2[lane];
    #pragma unroll
    for (int c = 0; c < TDD; c++) {
        t2 = fmaf(__shfl_sync(0xFFFFFFFF, t1, c), te_w2[c * TDD + lane], t2);
        m2 = fmaf(__shfl_sync(0xFFFFFFFF, m1, c), me_w2[c * TDD + lane], m2);
    }

    // ---- node fuse: h[2*lane], h[2*lane+1] ----
    const int k0 = 2 * lane;
    float2 hb = *(const float2*)&nf_b[k0];
    float h0 = hb.x, h1 = hb.y;
    #pragma unroll
    for (int c = 0; c < TDD; c++) {
        float hc = __shfl_sync(0xFFFFFFFF, t2, c);
        float2 wv = *(const float2*)&nf_w[c * HIDD + k0];
        h0 = fmaf(hc, wv.x, h0); h1 = fmaf(hc, wv.y, h1);
    }
    #pragma unroll
    for (int c = 0; c < TDD; c++) {
        float hc = __shfl_sync(0xFFFFFFFF, m2, c);
        float2 wv = *(const float2*)&nf_w[(TDD + c) * HIDD + k0];
        h0 = fmaf(hc, wv.x, h0); h1 = fmaf(hc, wv.y, h1);
    }
    h0 = fmaxf(h0, 0.f); h1 = fmaxf(h1, 0.f);
    *(float2*)&g_h[(size_t)node * HIDD + k0] = make_float2(h0, h1);

    // ---- P = h@w_i + ps_b1, Q = h@w_j ----
    float2 pb = *(const float2*)&ps_b1[k0];
    float p0 = pb.x, p1 = pb.y, q0 = 0.f, q1 = 0.f;
    #pragma unroll
    for (int cc = 0; cc < TDD; cc++) {
        float ha = __shfl_sync(0xFFFFFFFF, h0, cc);   // h[2cc]
        float hbv = __shfl_sync(0xFFFFFFFF, h1, cc);  // h[2cc+1]
        float2 wiA = *(const float2*)&ps_w1[(2 * cc) * HIDD + k0];
        float2 wiB = *(const float2*)&ps_w1[(2 * cc + 1) * HIDD + k0];
        float2 wjA = *(const float2*)&ps_w1[(HIDD + 2 * cc) * HIDD + k0];
        float2 wjB = *(const float2*)&ps_w1[(HIDD + 2 * cc + 1) * HIDD + k0];
        p0 = fmaf(ha, wiA.x, p0); p1 = fmaf(ha, wiA.y, p1);
        p0 = fmaf(hbv, wiB.x, p0); p1 = fmaf(hbv, wiB.y, p1);
        q0 = fmaf(ha, wjA.x, q0); q1 = fmaf(ha, wjA.y, q1);
        q0 = fmaf(hbv, wjB.x, q0); q1 = fmaf(hbv, wjB.y, q1);
    }
    *(float2*)&g_P[(size_t)node * HIDD + k0] = make_float2(p0, p1);
    *(float2*)&g_Q[(size_t)node * HIDD + k0] = make_float2(q0, q1);
}

// ---------------------------------------------------------------------------
// Kernel 2: pairwise delta via tf32 mma.sync. Merged N-halves: A built once
// per kt, 64 accumulator regs, B table packed uint4 (one LDS.128 -> 4 MMAs).
// ---------------------------------------------------------------------------
#define BF_BYTES (8 * 4 * 32 * 16)                   // uint4 table, 16 KB
#define SM_BYTES (BF_BYTES + (6 * 32 * PAD + 64) * 4)

__global__ __launch_bounds__(256, 2)
void pair_kernel(const float* __restrict__ ps_w1, const float* __restrict__ ps_w2,
                 const float* __restrict__ ps_b2, float* __restrict__ out)
{
    extern __shared__ __align__(16) char smx[];
    uint4* Bq = (uint4*)smx;                         // [kt][ntp][lane]
    float* fp = (float*)(smx + BF_BYTES);
    float* hI  = fp;                                 // [32][PAD]
    float* hJ  = hI + 32 * PAD;
    float* PI  = hJ + 32 * PAD;
    float* QI  = PI + 32 * PAD;
    float* PJ  = QI + 32 * PAD;
    float* QJ  = PJ + 32 * PAD;
    float* w2s = QJ + 32 * PAD;                      // [64]

    const int tid  = threadIdx.x;
    const int b    = blockIdx.y;
    const int w    = tid >> 5;
    const int lane = tid & 31;
    const int gid  = lane >> 2;                      // 0..7
    const int tig  = lane & 3;                       // 0..3

    // decode upper-triangular tile index
    int u = blockIdx.x, ti = 0;
    while (u >= NTILE - ti) { u -= NTILE - ti; ti++; }
    const int tj = ti + u;

    const int baseI = (b * NN + ti * 32) * HIDD;
    const int baseJ = (b * NN + tj * 32) * HIDD;

    for (int e = tid; e < 32 * HIDD; e += 256) {
        int r = e >> 6, c = e & 63;
        hI[r * PAD + c] = g_h[baseI + e];
        hJ[r * PAD + c] = g_h[baseJ + e];
        PI[r * PAD + c] = g_P[baseI + e];
        QI[r * PAD + c] = g_Q[baseI + e];
        PJ[r * PAD + c] = g_P[baseJ + e];
        QJ[r * PAD + c] = g_Q[baseJ + e];
    }
    // B fragment table (uint4): for kt (0..7), ntp (0..3), lane:
    //   {w_d[kt*8+tg][n0], w_d[kt*8+tg+4][n0], w_d[kt*8+tg][n1], w_d[kt*8+tg+4][n1]}
    //   where n0 = (2*ntp)*8+gd, n1 = (2*ntp+1)*8+gd, gd=lane>>2, tg=lane&3.
    for (int e = tid; e < 8 * 4 * 32; e += 256) {
        int ktp = e >> 5, ln = e & 31;
        int kt = ktp >> 2, ntp = ktp & 3;
        int gd = ln >> 2, tg = ln & 3;
        int c0 = kt * 8 + tg;
        int n0 = (2 * ntp) * 8 + gd, n1 = (2 * ntp + 1) * 8 + gd;
        uint4 v;
        v.x = f2tf32(ps_w1[(128 + c0) * HIDD + n0]);
        v.y = f2tf32(ps_w1[(128 + c0 + 4) * HIDD + n0]);
        v.z = f2tf32(ps_w1[(128 + c0) * HIDD + n1]);
        v.w = f2tf32(ps_w1[(128 + c0 + 4) * HIDD + n1]);
        Bq[(size_t)ktp * 32 + ln] = v;
    }
    if (tid < 64) w2s[tid] = ps_w2[tid];
    const float b2v = ps_b2[0];
    __syncthreads();

    float* ob = out + (size_t)b * NN * NN;

    #pragma unroll 1
    for (int it = 0; it < 4; it++) {
        const int i  = it * 8 + w;                   // warp-uniform tile row
        const int iP = i * PAD;

        float acc[2][8][4];
        #pragma unroll
        for (int mt = 0; mt < 2; mt++)
            #pragma unroll
            for (int n = 0; n < 8; n++)
                #pragma unroll
                for (int x = 0; x < 4; x++) acc[mt][n][x] = 0.f;

        const int r0 = gid * PAD, r1 = (gid + 8) * PAD,
                  r2 = (gid + 16) * PAD, r3 = (gid + 24) * PAD;

        #pragma unroll
        for (int kt = 0; kt < 8; kt++) {
            const int c0 = kt * 8 + tig, c1 = c0 + 4;
            const float hi0 = hI[iP + c0], hi1 = hI[iP + c1];
            uint32_t A00 = f2tf32(fabsf(hi0 - hJ[r0 + c0]));
            uint32_t A01 = f2tf32(fabsf(hi0 - hJ[r1 + c0]));
            uint32_t A02 = f2tf32(fabsf(hi1 - hJ[r0 + c1]));
            uint32_t A03 = f2tf32(fabsf(hi1 - hJ[r1 + c1]));
            uint32_t A10 = f2tf32(fabsf(hi0 - hJ[r2 + c0]));
            uint32_t A11 = f2tf32(fabsf(hi0 - hJ[r3 + c0]));
            uint32_t A12 = f2tf32(fabsf(hi1 - hJ[r2 + c1]));
            uint32_t A13 = f2tf32(fabsf(hi1 - hJ[r3 + c1]));
            #pragma unroll
            for (int ntp = 0; ntp < 4; ntp++) {
                uint4 bv = Bq[(size_t)(kt * 4 + ntp) * 32 + lane];
                mma_tf32(acc[0][2 * ntp],     A00, A01, A02, A03, bv.x, bv.y);
                mma_tf32(acc[1][2 * ntp],     A10, A11, A12, A13, bv.x, bv.y);
                mma_tf32(acc[0][2 * ntp + 1], A00, A01, A02, A03, bv.z, bv.w);
                mma_tf32(acc[1][2 * ntp + 1], A10, A11, A12, A13, bv.z, bv.w);
            }
        }

        // epilogue
        float sij[4], sji[4];
        #pragma unroll
        for (int rr = 0; rr < 4; rr++) { sij[rr] = 0.f; sji[rr] = 0.f; }

        #pragma unroll
        for (int nt = 0; nt < 8; nt++) {
            const int k0 = nt * 8 + tig * 2;
            const float2 piv = *(const float2*)&PI[iP + k0];
            const float2 qiv = *(const float2*)&QI[iP + k0];
            const float2 w2v = *(const float2*)&w2s[k0];
            #pragma unroll
            for (int rr = 0; rr < 4; rr++) {
                const int row = gid + 8 * rr;
                const float dk0 = acc[rr >> 1][nt][(rr & 1) * 2];
                const float dk1 = acc[rr >> 1][nt][(rr & 1) * 2 + 1];
                const float2 qjv = *(const float2*)&QJ[row * PAD + k0];
                const float2 pjv = *(const float2*)&PJ[row * PAD + k0];
                sij[rr] = fmaf(fmaxf(dk0 + piv.x + qjv.x, 0.f), w2v.x, sij[rr]);
                sij[rr] = fmaf(fmaxf(dk1 + piv.y + qjv.y, 0.f), w2v.y, sij[rr]);
                sji[rr] = fmaf(fmaxf(dk0 + pjv.x + qiv.x, 0.f), w2v.x, sji[rr]);
                sji[rr] = fmaf(fmaxf(dk1 + pjv.y + qiv.y, 0.f), w2v.y, sji[rr]);
            }
        }

        // quad reduction; bias added once after
        #pragma unroll
        for (int rr = 0; rr < 4; rr++) {
            sij[rr] += __shfl_xor_sync(0xFFFFFFFF, sij[rr], 1);
            sij[rr] += __shfl_xor_sync(0xFFFFFFFF, sij[rr], 2);
            sji[rr] += __shfl_xor_sync(0xFFFFFFFF, sji[rr], 1);
            sji[rr] += __shfl_xor_sync(0xFFFFFFFF, sji[rr], 2);
        }

        const int j  = gid + 8 * tig;
        const int gi = ti * 32 + i, gj = tj * 32 + j;
        const float a_ij = sij[tig] + b2v;
        const float a_ji = sji[tig] + b2v;
        if (ti != tj || i < j) {
            float d = 0.5f * (tanhf(a_ij) + tanhf(a_ji));
            ob[(size_t)gi * NN + gj] = d;
            ob[(size_t)gj * NN + gi] = d;
        } else if (i == j) {
            ob[(size_t)gi * NN + gj] = 0.f;
        }
    }
}

// ---------------------------------------------------------------------------
// Kernel 3: a = relu(a_static + lam*delta); row-normalize; write lam.
// ---------------------------------------------------------------------------
__global__ __launch_bounds__(256)
void finalize_kernel(const float* __restrict__ a_static,
                     const float* __restrict__ raw_lambda,
                     float* __restrict__ out, int out_size)
{
    const int row = blockIdx.x;
    const int b = row / NN, i = row % NN;
    const int tid = threadIdx.x;

    const float lam = 1.f / (1.f + expf(-raw_lambda[0]));
    float* orow = out + ((size_t)b * NN + i) * NN;
    const float* arow = a_static + (size_t)i * NN;

    float v[3];
    float s = 0.f;
    #pragma unroll
    for (int r = 0; r < 3; r++) {
        int j = tid + 256 * r;
        float a = fmaxf(fmaf(lam, orow[j], arow[j]), 0.f);
        v[r] = a;
        s += a;
    }

    __shared__ float red[256];
    red[tid] = s;
    __syncthreads();
    for (int off = 128; off > 0; off >>= 1) {
        if (tid < off) red[tid] += red[tid + off];
        __syncthreads();
    }
    float inv = 1.f / fmaxf(red[0], 1e-6f);
    #pragma unroll
    for (int r = 0; r < 3; r++) orow[tid + 256 * r] = v[r] * inv;

    if (row == 0 && tid == 0) {
        for (int idx = BB * NN * NN; idx < out_size; idx++) out[idx] = lam;
    }
}

// ---------------------------------------------------------------------------
extern "C" void kernel_launch(void* const* d_in, const int* in_sizes, int n_in,
                              void* d_out, int out_size)
{
    const float* x_hist   = (const float*)d_in[0];
    const float* x_mark   = (const float*)d_in[1];
    const float* a_static = (const float*)d_in[2];
    const float* te_w1 = (const float*)d_in[3];
    const float* te_b1 = (const float*)d_in[4];
    const float* te_w2 = (const float*)d_in[5];
    const float* te_b2 = (const float*)d_in[6];
    const float* me_w1 = (const float*)d_in[7];
    const float* me_b1 = (const float*)d_in[8];
    const float* me_w2 = (const float*)d_in[9];
    const float* me_b2 = (const float*)d_in[10];
    const float* nf_w  = (const float*)d_in[11];
    const float* nf_b  = (const float*)d_in[12];
    const float* ps_w1 = (const float*)d_in[13];
    const float* ps_b1 = (const float*)d_in[14];
    const float* ps_w2 = (const float*)d_in[15];
    const float* ps_b2 = (const float*)d_in[16];
    const float* raw_lambda = (const float*)d_in[17];
    float* out = (float*)d_out;

    static bool attr_set = false;
    if (!attr_set) {
        cudaFuncSetAttribute(pair_kernel,
                             cudaFuncAttributeMaxDynamicSharedMemorySize, SM_BYTES);
        attr_set = true;
    }

    node_kernel<<<BB * NN / 8, 256>>>(x_hist, x_mark, te_w1, te_b1, te_w2, te_b2,
                                      me_w1, me_b1, me_w2, me_b2, nf_w, nf_b,
                                      ps_w1, ps_b1);

    dim3 grid2(NUPPER, BB);
    pair_kernel<<<grid2, 256, SM_BYTES>>>(ps_w1, ps_w2, ps_b2, out);

    finalize_kernel<<<BB * NN, 256>>>(a_static, raw_lambda, out, out_size);
}